// round 14
// baseline (speedup 1.0000x reference)
#include <cuda_runtime.h>
#include <math.h>

typedef unsigned long long u64;
typedef unsigned int u32;

// Problem dims
#define B_  256
#define S_  2048
#define I_  32
#define H_  18

// Scan pipeline config: 4 temporal segments, 3 merged roles, CH=8.
#define CH      8                // timesteps per chunk
#define NSEG    4
#define SEGSTEP (S_ / NSEG)      // 512 new steps per segment
#define BURN    128              // burn-in steps (segments 1..3)
#define BURNC   (BURN / CH)      // 16 burn-in chunks
#define NC0     (SEGSTEP / CH)   // 64 chunks (segment 0, no burn-in)
#define NCX     ((SEGSTEP + BURN) / CH)  // 80 chunks (segments 1..3)
#define RS2     10               // ring row stride in u64 (80 bytes)
#define ROWB    80
#define XCHB    (CH * 128)       // bytes per x chunk buffer (8 rows x 128B)

// Scratch: layer-2 hidden sequence [B, S, H] f32 (36 MB).
__device__ float g_h2[(size_t)B_ * S_ * H_];

// ---------------- packed f32x2 helpers ----------------
__device__ __forceinline__ void fma2(u64& d, u64 a, u64 b) {
    asm("fma.rn.f32x2 %0, %1, %2, %0;" : "+l"(d) : "l"(a), "l"(b));
}
__device__ __forceinline__ u64 add2(u64 a, u64 b) {
    u64 d; asm("add.rn.f32x2 %0, %1, %2;" : "=l"(d) : "l"(a), "l"(b)); return d;
}
__device__ __forceinline__ float hsum2(u64 a) {
    float x, y; asm("mov.b64 {%0, %1}, %2;" : "=f"(x), "=f"(y) : "l"(a));
    return x + y;
}
__device__ __forceinline__ u64 pack2(float x, float y) {
    u64 d; asm("mov.b64 %0, {%1, %2};" : "=l"(d) : "f"(x), "f"(y)); return d;
}
__device__ __forceinline__ float tanh_fast(float x) {
    float r; asm("tanh.approx.f32 %0, %1;" : "=f"(r) : "f"(x)); return r;
}
// Ordered shared ops (same-warp in-order smem pipe; volatile pins order).
__device__ __forceinline__ void sts_f32(u32 addr, float v) {
    asm volatile("st.shared.f32 [%0], %1;" :: "r"(addr), "f"(v));
}
__device__ __forceinline__ void sts_f128(u32 addr, float4 v) {
    asm volatile("st.shared.v4.f32 [%0], {%1,%2,%3,%4};"
                 :: "r"(addr), "f"(v.x), "f"(v.y), "f"(v.z), "f"(v.w));
}
__device__ __forceinline__ u64 lds_u64(u32 addr) {
    u64 v; asm volatile("ld.shared.b64 %0, [%1];" : "=l"(v) : "r"(addr)); return v;
}
__device__ __forceinline__ void lds_pair(u32 addr, u64& x, u64& y) {
    asm volatile("ld.shared.v2.b64 {%0,%1}, [%2];" : "=l"(x), "=l"(y) : "r"(addr));
}

struct Acc { u64 a0, a1, a2; };

// 18-value dot from a ring row at smem addr `hp` (16B-aligned).
__device__ __forceinline__ void rowdot(Acc& A, const u64* w, u32 hp) {
    u64 v0, v1, v2, v3, v4, v5, v6, v7, v8;
    lds_pair(hp,      v0, v1);
    lds_pair(hp + 16, v2, v3);
    lds_pair(hp + 32, v4, v5);
    lds_pair(hp + 48, v6, v7);
    v8 = lds_u64(hp + 64);
    fma2(A.a0, w[0], v0); fma2(A.a1, w[1], v1); fma2(A.a2, w[2], v2);
    fma2(A.a0, w[3], v3); fma2(A.a1, w[4], v4); fma2(A.a2, w[5], v5);
    fma2(A.a0, w[6], v6); fma2(A.a1, w[7], v7); fma2(A.a2, w[8], v8);
}
__device__ __forceinline__ float finish(Acc& A) {
    return tanh_fast(hsum2(add2(add2(A.a0, A.a1), A.a2)));
}

// ---------------------------------------------------------------------------
// Kernel A: fused 3-layer RNN scan, 4-way temporal segmentation.
// 3 roles (= layers; x-transform merged into layer-0's warp) x 8 chains
// (2 batches x 4 segments) = 24 warps (768 thr). Grid 128 = one wave.
// wid = role*8 + k  ->  chain k's 3 role-warps all on SMSP (k&3); 2 chains
// (k, k+4) per SMSP -> 6 warps/SMSP. Per-chain named barriers decouple chains.
// ---------------------------------------------------------------------------
__global__ __launch_bounds__(768, 1)
void rnn_scan_kernel(const float* __restrict__ input,
                     const float* __restrict__ hidden,
                     const float* __restrict__ Wih0, const float* __restrict__ bih0,
                     const float* __restrict__ Whh0, const float* __restrict__ bhh0,
                     const float* __restrict__ Wih1, const float* __restrict__ bih1,
                     const float* __restrict__ Whh1, const float* __restrict__ bhh1,
                     const float* __restrict__ Wih2, const float* __restrict__ bih2,
                     const float* __restrict__ Whh2, const float* __restrict__ bhh2,
                     float* __restrict__ out, int write_hidden)
{
    __shared__ __align__(16) float4 s_x [8][2][CH][8];    // x double buffer
    __shared__ __align__(16) u64    s_h0[8][2][CH][RS2];  // layer0 -> layer1 (+self)
    __shared__ __align__(16) u64    s_h1[8][2][CH][RS2];  // layer1 -> layer2 (+self)
    __shared__ __align__(16) u64    s_h2[8][2][CH][RS2];  // layer2 self
    // 16384 + 3*10240 = 47104 B static (< 48KB)

    const int tid  = threadIdx.x;
    const int wid  = tid >> 5;
    const int lane = tid & 31;
    const int k    = wid & 7;                   // chain index; SMSP = k&3
    const int role = wid >> 3;                  // 0..2 = layer
    const int bi   = k & 1;
    const int sg   = k >> 1;                    // segment 0..3
    const int b    = blockIdx.x * 2 + bi;
    const int jj   = (lane < H_) ? lane : 0;    // clamped; dup lanes benign
    const bool act = (lane < H_);

    const int base_t = sg ? (sg * SEGSTEP - BURN) : 0;
    const int NCH    = sg ? NCX : NC0;

    u64 wA[16];      // layer0 input weight pairs
    u64 wP[9];       // layers 1/2 input-transform weight pairs
    u64 wR[9];       // recurrent weight pairs
    float bsum = 0.f, h = 0.f;

    if (role == 0) {
        const u64* wa = (const u64*)(Wih0 + jj * I_);
        const u64* wr = (const u64*)(Whh0 + jj * H_);
        #pragma unroll
        for (int m = 0; m < 16; ++m) wA[m] = __ldg(&wa[m]);
        #pragma unroll
        for (int m = 0; m < 9; ++m) wR[m] = __ldg(&wr[m]);
        bsum = __ldg(&bih0[jj]) + __ldg(&bhh0[jj]);
        h = sg ? 0.f : __ldg(&hidden[0 * B_ * H_ + b * H_ + jj]);
        ((float*)&s_h0[k][1][CH - 1][0])[jj] = h;        // seed c=-1 (own warp)
    } else if (role == 1) {
        const u64* wp = (const u64*)(Wih1 + jj * H_);
        const u64* wr = (const u64*)(Whh1 + jj * H_);
        #pragma unroll
        for (int m = 0; m < 9; ++m) { wP[m] = __ldg(&wp[m]); wR[m] = __ldg(&wr[m]); }
        bsum = __ldg(&bih1[jj]) + __ldg(&bhh1[jj]);
        h = sg ? 0.f : __ldg(&hidden[1 * B_ * H_ + b * H_ + jj]);
        ((float*)&s_h1[k][1][CH - 1][0])[jj] = h;
    } else {
        const u64* wp = (const u64*)(Wih2 + jj * H_);
        const u64* wr = (const u64*)(Whh2 + jj * H_);
        #pragma unroll
        for (int m = 0; m < 9; ++m) { wP[m] = __ldg(&wp[m]); wR[m] = __ldg(&wr[m]); }
        bsum = __ldg(&bih2[jj]) + __ldg(&bhh2[jj]);
        h = sg ? 0.f : __ldg(&hidden[2 * B_ * H_ + b * H_ + jj]);
        ((float*)&s_h2[k][1][CH - 1][0])[jj] = h;
    }
    const u64 binit = pack2(bsum, 0.f);

    u32 self_base = 0, pv_base = 0;
    const u32 x_base = (u32)__cvta_generic_to_shared(&s_x[k][0][0][0]);
    if (role == 0) {
        self_base = (u32)__cvta_generic_to_shared(&s_h0[k][0][0][0]);
    } else if (role == 1) {
        self_base = (u32)__cvta_generic_to_shared(&s_h1[k][0][0][0]);
        pv_base   = (u32)__cvta_generic_to_shared(&s_h0[k][0][0][0]);
    } else {
        self_base = (u32)__cvta_generic_to_shared(&s_h2[k][0][0][0]);
        pv_base   = (u32)__cvta_generic_to_shared(&s_h1[k][0][0][0]);
    }

    // role0: preload chunk 0 into x buffer 0 (8 rows x 128B = 64 float4).
    float4 xr[2];
    if (role == 0) {
        const float4* xg = (const float4*)(input + ((size_t)b * S_ + base_t) * I_);
        #pragma unroll
        for (int i = 0; i < 2; ++i) xr[i] = __ldg(&xg[lane + 32 * i]);
        #pragma unroll
        for (int i = 0; i < 2; ++i)
            sts_f128(x_base + (u32)(lane + 32 * i) * 16, xr[i]);
    }

    for (int ss = 0; ss < NCX + 2; ++ss) {
        const int c = ss - role;
        if ((unsigned)c < (unsigned)NCH) {
            const int slot = c & 1;
            const int t0   = base_t + c * CH;
            if (role == 0) {
                // Prefetch next chunk's x early (latency hides behind steps).
                const bool pf = (c + 1) < NCH;
                if (pf) {
                    const float4* xg =
                        (const float4*)(input + ((size_t)b * S_ + t0 + CH) * I_);
                    #pragma unroll
                    for (int i = 0; i < 2; ++i) xr[i] = __ldg(&xg[lane + 32 * i]);
                }
                u32 xa  = x_base + slot * XCHB;
                u32 hp  = self_base + ((slot ^ 1) * CH + CH - 1) * ROWB;
                u32 cur = self_base + slot * CH * ROWB;
                #pragma unroll 4
                for (int t = 0; t < CH; ++t) {
                    u64 x0, x1, x2, x3, x4, x5, x6, x7;
                    u64 x8, x9, xA, xB, xC, xD, xE, xF;
                    lds_pair(xa,       x0, x1);  lds_pair(xa + 16,  x2, x3);
                    lds_pair(xa + 32,  x4, x5);  lds_pair(xa + 48,  x6, x7);
                    lds_pair(xa + 64,  x8, x9);  lds_pair(xa + 80,  xA, xB);
                    lds_pair(xa + 96,  xC, xD);  lds_pair(xa + 112, xE, xF);
                    u64 a0 = binit, a1 = 0ull, a2 = 0ull, a3 = 0ull;
                    fma2(a0, wA[0],  x0); fma2(a1, wA[1],  x1);
                    fma2(a2, wA[2],  x2); fma2(a3, wA[3],  x3);
                    fma2(a0, wA[4],  x4); fma2(a1, wA[5],  x5);
                    fma2(a2, wA[6],  x6); fma2(a3, wA[7],  x7);
                    fma2(a0, wA[8],  x8); fma2(a1, wA[9],  x9);
                    fma2(a2, wA[10], xA); fma2(a3, wA[11], xB);
                    fma2(a0, wA[12], xC); fma2(a1, wA[13], xD);
                    fma2(a2, wA[14], xE); fma2(a3, wA[15], xF);
                    a0 = add2(a0, a1); a2 = add2(a2, a3); a0 = add2(a0, a2);
                    const float pre = hsum2(a0);
                    Acc A = { pack2(pre, 0.f), 0ull, 0ull };
                    rowdot(A, wR, hp);
                    h = finish(A);
                    sts_f32(cur + 4 * jj, h);
                    hp = cur; cur += ROWB; xa += 128;
                }
                if (pf) {
                    const u32 dst = x_base + ((c + 1) & 1) * XCHB;
                    #pragma unroll
                    for (int i = 0; i < 2; ++i)
                        sts_f128(dst + (u32)(lane + 32 * i) * 16, xr[i]);
                }
            } else {
                u32 hp  = self_base + ((slot ^ 1) * CH + CH - 1) * ROWB;
                u32 cur = self_base + slot * CH * ROWB;
                u32 pva = pv_base + slot * CH * ROWB;
                float* go = g_h2 + ((size_t)b * S_ + t0) * H_;
                const bool wr = (role == 2) && ((!sg) || (c >= BURNC));
                #pragma unroll 4
                for (int t = 0; t < CH; ++t) {
                    Acc A = { binit, 0ull, 0ull };
                    rowdot(A, wP, pva);      // producer row (barrier-separated)
                    rowdot(A, wR, hp);       // self row (same-warp ordered)
                    h = finish(A);
                    sts_f32(cur + 4 * jj, h);
                    if (wr) go[t * H_ + jj] = h;     // off-chain
                    hp = cur; cur += ROWB; pva += ROWB;
                }
            }
        }
        // Per-chain named barrier: 3 warps (96 threads) of chain k.
        asm volatile("bar.sync %0, %1;" :: "r"(k + 1), "r"(96) : "memory");
    }

    // Final hidden states come from segment-3 chains; role == layer.
    if (write_hidden && sg == 3 && act)
        out[(size_t)B_ * S_ + (size_t)role * B_ * H_ + b * H_ + lane] = h;
}

// ---------------------------------------------------------------------------
// Kernel B: MLP head (unchanged from best).
// ---------------------------------------------------------------------------
__global__ __launch_bounds__(256, 5)
void mlp_head_kernel(const float* __restrict__ W1, const float* __restrict__ b1,
                     const float* __restrict__ W2, const float* __restrict__ b2,
                     const float* __restrict__ W3, const float* __restrict__ b3,
                     const float* __restrict__ W4, const float* __restrict__ b4,
                     const float* __restrict__ W5, const float* __restrict__ b5,
                     const float* __restrict__ W6, const float* __restrict__ b6,
                     float* __restrict__ out)
{
    __shared__ u64 sROW[256 * 9];
    __shared__ u64 sW1[162], sW2[90], sW3[40], sW4[16], sW5[4];
    __shared__ float sb1[18], sb2[10], sb3[8], sb4[4], sb5[2], sW6f[2], sb6f[1];

    const int tid = threadIdx.x;
    if (tid < 162) sW1[tid] = __ldg((const u64*)W1 + tid);
    if (tid < 90)  sW2[tid] = __ldg((const u64*)W2 + tid);
    if (tid < 40)  sW3[tid] = __ldg((const u64*)W3 + tid);
    if (tid < 16)  sW4[tid] = __ldg((const u64*)W4 + tid);
    if (tid < 4)  { sW5[tid] = __ldg((const u64*)W5 + tid); sb4[tid] = b4[tid]; }
    if (tid < 18)  sb1[tid] = b1[tid];
    if (tid < 10)  sb2[tid] = b2[tid];
    if (tid < 8)   sb3[tid] = b3[tid];
    if (tid < 2)  { sb5[tid] = b5[tid]; sW6f[tid] = W6[tid]; }
    if (tid == 0)  sb6f[0] = b6[0];

    const size_t base = (size_t)blockIdx.x * 256;
    const u64* gh = (const u64*)g_h2 + base * 9;
    #pragma unroll
    for (int i = 0; i < 9; ++i) sROW[tid + i * 256] = __ldg(&gh[tid + i * 256]);
    __syncthreads();

    u64 a0[9];
    #pragma unroll
    for (int m = 0; m < 9; ++m) a0[m] = sROW[tid * 9 + m];

    float a1[18];
    #pragma unroll
    for (int j = 0; j < 18; ++j) {
        u64 acc = pack2(sb1[j], 0.f), accb = 0ull;
        #pragma unroll
        for (int m = 0; m < 9; ++m) fma2((m & 1) ? accb : acc, sW1[j * 9 + m], a0[m]);
        a1[j] = fmaxf(hsum2(add2(acc, accb)), 0.f);
    }
    u64 a1p[9];
    #pragma unroll
    for (int m = 0; m < 9; ++m) a1p[m] = pack2(a1[2 * m], a1[2 * m + 1]);

    float a2[10];
    #pragma unroll
    for (int j = 0; j < 10; ++j) {
        u64 acc = pack2(sb2[j], 0.f), accb = 0ull;
        #pragma unroll
        for (int m = 0; m < 9; ++m) fma2((m & 1) ? accb : acc, sW2[j * 9 + m], a1p[m]);
        a2[j] = fmaxf(hsum2(add2(acc, accb)), 0.f);
    }
    u64 a2p[5];
    #pragma unroll
    for (int m = 0; m < 5; ++m) a2p[m] = pack2(a2[2 * m], a2[2 * m + 1]);

    float a3[8];
    #pragma unroll
    for (int j = 0; j < 8; ++j) {
        u64 acc = pack2(sb3[j], 0.f), accb = 0ull;
        #pragma unroll
        for (int m = 0; m < 5; ++m) fma2((m & 1) ? accb : acc, sW3[j * 5 + m], a2p[m]);
        a3[j] = fmaxf(hsum2(add2(acc, accb)), 0.f);
    }
    u64 a3p[4];
    #pragma unroll
    for (int m = 0; m < 4; ++m) a3p[m] = pack2(a3[2 * m], a3[2 * m + 1]);

    float a4[4];
    #pragma unroll
    for (int j = 0; j < 4; ++j) {
        u64 acc = pack2(sb4[j], 0.f), accb = 0ull;
        #pragma unroll
        for (int m = 0; m < 4; ++m) fma2((m & 1) ? accb : acc, sW4[j * 4 + m], a3p[m]);
        a4[j] = fmaxf(hsum2(add2(acc, accb)), 0.f);
    }
    u64 a4p[2] = { pack2(a4[0], a4[1]), pack2(a4[2], a4[3]) };

    float a5[2];
    #pragma unroll
    for (int j = 0; j < 2; ++j) {
        u64 acc = pack2(sb5[j], 0.f);
        fma2(acc, sW5[j * 2 + 0], a4p[0]);
        fma2(acc, sW5[j * 2 + 1], a4p[1]);
        a5[j] = fmaxf(hsum2(acc), 0.f);
    }
    out[base + tid] = fmaf(a5[0], sW6f[0], fmaf(a5[1], sW6f[1], sb6f[0]));
}

// ---------------------------------------------------------------------------
// Launch
// ---------------------------------------------------------------------------
extern "C" void kernel_launch(void* const* d_in, const int* in_sizes, int n_in,
                              void* d_out, int out_size)
{
    const float* input  = (const float*)d_in[0];
    const float* hidden = (const float*)d_in[1];
    const float* Wih0 = (const float*)d_in[2];
    const float* bih0 = (const float*)d_in[3];
    const float* Whh0 = (const float*)d_in[4];
    const float* bhh0 = (const float*)d_in[5];
    const float* Wih1 = (const float*)d_in[6];
    const float* bih1 = (const float*)d_in[7];
    const float* Whh1 = (const float*)d_in[8];
    const float* bhh1 = (const float*)d_in[9];
    const float* Wih2 = (const float*)d_in[10];
    const float* bih2 = (const float*)d_in[11];
    const float* Whh2 = (const float*)d_in[12];
    const float* bhh2 = (const float*)d_in[13];
    const float* W1 = (const float*)d_in[14];
    const float* b1 = (const float*)d_in[15];
    const float* W2 = (const float*)d_in[16];
    const float* b2 = (const float*)d_in[17];
    const float* W3 = (const float*)d_in[18];
    const float* b3 = (const float*)d_in[19];
    const float* W4 = (const float*)d_in[20];
    const float* b4 = (const float*)d_in[21];
    const float* W5 = (const float*)d_in[22];
    const float* b5 = (const float*)d_in[23];
    const float* W6 = (const float*)d_in[24];
    const float* b6 = (const float*)d_in[25];

    float* out = (float*)d_out;
    const int write_hidden = (out_size >= B_ * S_ + 3 * B_ * H_) ? 1 : 0;

    rnn_scan_kernel<<<B_ / 2, 768>>>(input, hidden,
                                     Wih0, bih0, Whh0, bhh0,
                                     Wih1, bih1, Whh1, bhh1,
                                     Wih2, bih2, Whh2, bhh2,
                                     out, write_hidden);

    mlp_head_kernel<<<(B_ * S_) / 256, 256>>>(W1, b1, W2, b2, W3, b3,
                                              W4, b4, W5, b5, W6, b6, out);
}

// round 15
// speedup vs baseline: 1.2300x; 1.2300x over previous
#include <cuda_runtime.h>
#include <math.h>

typedef unsigned long long u64;
typedef unsigned int u32;

// Problem dims
#define B_  256
#define S_  2048
#define I_  32
#define H_  18

// Fused-scan config: 4 temporal segments, 1 warp per chain (3 layers skewed).
#define NSEG    4
#define SEGSTEP (S_ / NSEG)      // 512 new steps per segment
#define BURN    128              // burn-in steps (segments 1..3)
#define RS2     10               // ring row stride in u64 (80 bytes)
#define ROWB    80

// Scratch
__device__ float g_h2[(size_t)B_ * S_ * H_];   // layer-2 hidden sequence
__device__ float g_xw[(size_t)B_ * S_ * H_];   // Wih0·x + bih0 + bhh0

// ---------------- packed f32x2 helpers ----------------
__device__ __forceinline__ void fma2(u64& d, u64 a, u64 b) {
    asm("fma.rn.f32x2 %0, %1, %2, %0;" : "+l"(d) : "l"(a), "l"(b));
}
__device__ __forceinline__ u64 add2(u64 a, u64 b) {
    u64 d; asm("add.rn.f32x2 %0, %1, %2;" : "=l"(d) : "l"(a), "l"(b)); return d;
}
__device__ __forceinline__ float hsum2(u64 a) {
    float x, y; asm("mov.b64 {%0, %1}, %2;" : "=f"(x), "=f"(y) : "l"(a));
    return x + y;
}
__device__ __forceinline__ u64 pack2(float x, float y) {
    u64 d; asm("mov.b64 %0, {%1, %2};" : "=l"(d) : "f"(x), "f"(y)); return d;
}
__device__ __forceinline__ float tanh_fast(float x) {
    float r; asm("tanh.approx.f32 %0, %1;" : "=f"(r) : "f"(x)); return r;
}
// Ordered shared ops (same-warp in-order smem pipe; volatile pins order).
__device__ __forceinline__ void sts_f32(u32 addr, float v) {
    asm volatile("st.shared.f32 [%0], %1;" :: "r"(addr), "f"(v));
}
__device__ __forceinline__ u64 lds_u64(u32 addr) {
    u64 v; asm volatile("ld.shared.b64 %0, [%1];" : "=l"(v) : "r"(addr)); return v;
}
__device__ __forceinline__ void lds_pair(u32 addr, u64& x, u64& y) {
    asm volatile("ld.shared.v2.b64 {%0,%1}, [%2];" : "=l"(x), "=l"(y) : "r"(addr));
}
__device__ __forceinline__ float lds_f32(u32 addr) {
    float v; asm volatile("ld.shared.f32 %0, [%1];" : "=f"(v) : "r"(addr)); return v;
}

struct Acc { u64 a0, a1, a2; };

__device__ __forceinline__ void load_row(u32 a, u64* v) {
    lds_pair(a,      v[0], v[1]);
    lds_pair(a + 16, v[2], v[3]);
    lds_pair(a + 32, v[4], v[5]);
    lds_pair(a + 48, v[6], v[7]);
    v[8] = lds_u64(a + 64);
}
__device__ __forceinline__ void dot9r(Acc& A, const u64* w, const u64* v) {
    fma2(A.a0, w[0], v[0]); fma2(A.a1, w[1], v[1]); fma2(A.a2, w[2], v[2]);
    fma2(A.a0, w[3], v[3]); fma2(A.a1, w[4], v[4]); fma2(A.a2, w[5], v[5]);
    fma2(A.a0, w[6], v[6]); fma2(A.a1, w[7], v[7]); fma2(A.a2, w[8], v[8]);
}
__device__ __forceinline__ float finish(Acc& A) {
    return tanh_fast(hsum2(add2(add2(A.a0, A.a1), A.a2)));
}

// ---------------------------------------------------------------------------
// Kernel 0: g_xw[b,t,:] = Wih0 · x[b,t,:] + bih0 + bhh0.
// Thread-per-row, weights broadcast from smem, coalesced out via smem bounce.
// ---------------------------------------------------------------------------
__global__ __launch_bounds__(128)
void xw0_kernel(const float* __restrict__ input,
                const float* __restrict__ Wih0,
                const float* __restrict__ bih0,
                const float* __restrict__ bhh0)
{
    __shared__ u64 sW[288];              // 18x32 f
    __shared__ float sB[18];
    __shared__ u64 sOut[128 * 9];        // 128 rows x 18 f

    const int tid = threadIdx.x;
    sW[tid] = __ldg((const u64*)Wih0 + tid);
    sW[tid + 128] = __ldg((const u64*)Wih0 + tid + 128);
    if (tid < 32) sW[tid + 256] = __ldg((const u64*)Wih0 + tid + 256);
    if (tid < 18) sB[tid] = __ldg(&bih0[tid]) + __ldg(&bhh0[tid]);
    __syncthreads();

    const size_t row = (size_t)blockIdx.x * 128 + tid;
    const u64* xr = (const u64*)(input + row * I_);
    u64 xv[16];
    #pragma unroll
    for (int m = 0; m < 16; ++m) xv[m] = __ldg(&xr[m]);

    float* sOutF = (float*)sOut;
    #pragma unroll
    for (int j = 0; j < 18; ++j) {
        u64 acc = pack2(sB[j], 0.f), accb = 0ull;
        #pragma unroll
        for (int m = 0; m < 16; ++m) fma2((m & 1) ? accb : acc, sW[j * 16 + m], xv[m]);
        sOutF[tid * 18 + j] = hsum2(add2(acc, accb));
    }
    __syncthreads();

    u64* go = (u64*)g_xw + (size_t)blockIdx.x * (128 * 9);
    #pragma unroll
    for (int k2 = 0; k2 < 9; ++k2) go[tid + k2 * 128] = sOut[tid + k2 * 128];
}

// ---------------------------------------------------------------------------
// Kernel A: fused 3-layer RNN scan, one warp per chain, layers time-skewed:
// at iteration i the warp computes h0[i], h1[i-1], h2[i-2].
//   rowH0 = h0[i-1] -> L0 recurrence + L1 input (shared loads)
//   rowH1 = h1[i-2] -> L1 recurrence + L2 input (shared loads)
//   rowH2 = h2[i-3] -> L2 recurrence
// Depth-2 rings, all intra-warp (volatile order), ZERO barriers.
// Block: 8 warps = 8 chains (2 batches x 4 segments). Grid 128 = one wave.
// ---------------------------------------------------------------------------

// One fused step. I is the iteration index (compile-time in unrolled chunks
// except the STG guard which is runtime-cheap). L1/L2 flags peel the pipe fill.
#define FSTEP(I, DO_L1, DO_L2, XWV) do {                                      \
    const u32 slo = ((I) & 1) * ROWB, spo = slo ^ ROWB;                       \
    u64 v_[9];                                                                \
    load_row(h0b + spo, v_);                    /* h0[i-1] */                 \
    Acc A0_ = { pack2((XWV), 0.f), 0ull, 0ull };                              \
    dot9r(A0_, wR0, v_);                                                      \
    Acc A1_ = { b1init, 0ull, 0ull };                                         \
    if (DO_L1) dot9r(A1_, wP1, v_);                                           \
    u64 u_[9];                                                                \
    if (DO_L1 || DO_L2) load_row(h1b + slo, u_); /* h1[i-2] */                \
    if (DO_L1) dot9r(A1_, wR1, u_);                                           \
    Acc A2_ = { b2init, 0ull, 0ull };                                         \
    if (DO_L2) {                                                              \
        dot9r(A2_, wP2, u_);                                                  \
        u64 z_[9];                                                            \
        load_row(h2b + spo, z_);                /* h2[i-3] */                 \
        dot9r(A2_, wR2, z_);                                                  \
    }                                                                         \
    float h0v_ = finish(A0_);                                                 \
    sts_f32(h0b + slo + 4 * jj, h0v_);                                        \
    if (DO_L1) {                                                              \
        float h1v_ = finish(A1_);                                             \
        sts_f32(h1b + spo + 4 * jj, h1v_);                                    \
    }                                                                         \
    if (DO_L2) {                                                              \
        float h2v_ = finish(A2_);                                             \
        sts_f32(h2b + slo + 4 * jj, h2v_);                                    \
        if ((I) >= wstart) go2[(size_t)((I) - 2) * H_] = h2v_;                \
    }                                                                         \
} while (0)

__global__ __launch_bounds__(256, 1)
void rnn_scan_kernel(const float* __restrict__ hidden,
                     const float* __restrict__ Whh0,
                     const float* __restrict__ Wih1, const float* __restrict__ bih1,
                     const float* __restrict__ Whh1, const float* __restrict__ bhh1,
                     const float* __restrict__ Wih2, const float* __restrict__ bih2,
                     const float* __restrict__ Whh2, const float* __restrict__ bhh2,
                     float* __restrict__ out, int write_hidden)
{
    __shared__ __align__(16) u64 s_h[8][3][2][RS2];   // per-chain depth-2 rings

    const int tid  = threadIdx.x;
    const int w    = tid >> 5;                // chain index 0..7
    const int lane = tid & 31;
    const int bi   = w & 1;
    const int sg   = w >> 1;                  // segment 0..3
    const int b    = blockIdx.x * 2 + bi;
    const int jj   = (lane < H_) ? lane : 0;  // clamped; dup lanes benign
    const bool act = (lane < H_);

    const int base_t = sg ? (sg * SEGSTEP - BURN) : 0;
    const int N      = sg ? (SEGSTEP + BURN) : SEGSTEP;   // 640 / 512
    const int wstart = sg ? (BURN + 2) : 2;               // first STG iteration

    // Weights (all three layers, lane jj's rows)
    u64 wR0[9], wP1[9], wR1[9], wP2[9], wR2[9];
    {
        const u64* p0 = (const u64*)(Whh0 + jj * H_);
        const u64* p1 = (const u64*)(Wih1 + jj * H_);
        const u64* p2 = (const u64*)(Whh1 + jj * H_);
        const u64* p3 = (const u64*)(Wih2 + jj * H_);
        const u64* p4 = (const u64*)(Whh2 + jj * H_);
        #pragma unroll
        for (int m = 0; m < 9; ++m) {
            wR0[m] = __ldg(&p0[m]); wP1[m] = __ldg(&p1[m]); wR1[m] = __ldg(&p2[m]);
            wP2[m] = __ldg(&p3[m]); wR2[m] = __ldg(&p4[m]);
        }
    }
    const u64 b1init = pack2(__ldg(&bih1[jj]) + __ldg(&bhh1[jj]), 0.f);
    const u64 b2init = pack2(__ldg(&bih2[jj]) + __ldg(&bhh2[jj]), 0.f);

    const u32 h0b = (u32)__cvta_generic_to_shared(&s_h[w][0][0][0]);
    const u32 h1b = (u32)__cvta_generic_to_shared(&s_h[w][1][0][0]);
    const u32 h2b = (u32)__cvta_generic_to_shared(&s_h[w][2][0][0]);

    // Seeds into slot 1 of each ring (first reads: h0 at i=0, h1 at i=1, h2 at i=2).
    {
        float h0i = sg ? 0.f : __ldg(&hidden[0 * B_ * H_ + b * H_ + jj]);
        float h1i = sg ? 0.f : __ldg(&hidden[1 * B_ * H_ + b * H_ + jj]);
        float h2i = sg ? 0.f : __ldg(&hidden[2 * B_ * H_ + b * H_ + jj]);
        sts_f32(h0b + ROWB + 4 * jj, h0i);
        sts_f32(h1b + ROWB + 4 * jj, h1i);
        sts_f32(h2b + ROWB + 4 * jj, h2i);
    }

    // xw stream: lane jj reads g_xw[b][base_t + i][jj]; prefetch 8 ahead.
    const float* xwp = g_xw + ((size_t)b * S_ + base_t) * H_ + jj;
    float* go2 = g_h2 + ((size_t)b * S_ + base_t) * H_ + jj;   // index (i-2)*H_

    float xcur[8], xnxt[8];
    #pragma unroll
    for (int u = 0; u < 8; ++u) xcur[u] = __ldg(&xwp[u * H_]);
    xwp += 8 * H_;

    const int nch = N >> 3;

    // ---- chunk 0 (i=0..7): pipe fill, guarded ----
    {
        #pragma unroll
        for (int u = 0; u < 8; ++u) xnxt[u] = __ldg(&xwp[u * H_]);
        xwp += 8 * H_;
        FSTEP(0, false, false, xcur[0]);
        FSTEP(1, true,  false, xcur[1]);
        FSTEP(2, true,  true,  xcur[2]);
        FSTEP(3, true,  true,  xcur[3]);
        FSTEP(4, true,  true,  xcur[4]);
        FSTEP(5, true,  true,  xcur[5]);
        FSTEP(6, true,  true,  xcur[6]);
        FSTEP(7, true,  true,  xcur[7]);
        #pragma unroll
        for (int u = 0; u < 8; ++u) xcur[u] = xnxt[u];
    }

    // ---- steady chunks ----
    for (int c = 1; c < nch; ++c) {
        const bool pf = (c + 1) < nch;
        if (pf) {
            #pragma unroll
            for (int u = 0; u < 8; ++u) xnxt[u] = __ldg(&xwp[u * H_]);
            xwp += 8 * H_;
        }
        const int i0 = c * 8;
        #pragma unroll
        for (int u = 0; u < 8; ++u) {
            FSTEP(i0 + u, true, true, xcur[u]);
        }
        if (pf) {
            #pragma unroll
            for (int u = 0; u < 8; ++u) xcur[u] = xnxt[u];
        }
    }

    // ---- epilogue: i = N (L1+L2), i = N+1 (L2) ----
    {
        const u32 slo = (N & 1) * ROWB, spo = slo ^ ROWB;
        u64 v_[9]; load_row(h0b + spo, v_);          // h0[N-1]
        Acc A1_ = { b1init, 0ull, 0ull };
        dot9r(A1_, wP1, v_);
        u64 u_[9]; load_row(h1b + slo, u_);          // h1[N-2]
        dot9r(A1_, wR1, u_);
        Acc A2_ = { b2init, 0ull, 0ull };
        dot9r(A2_, wP2, u_);
        u64 z_[9]; load_row(h2b + spo, z_);          // h2[N-3]
        dot9r(A2_, wR2, z_);
        float h1v_ = finish(A1_);
        sts_f32(h1b + spo + 4 * jj, h1v_);
        float h2v_ = finish(A2_);
        sts_f32(h2b + slo + 4 * jj, h2v_);
        go2[(size_t)(N - 2) * H_] = h2v_;
    }
    {
        const u32 slo = ((N + 1) & 1) * ROWB, spo = slo ^ ROWB;
        u64 u_[9]; load_row(h1b + slo, u_);          // h1[N-1]
        Acc A2_ = { b2init, 0ull, 0ull };
        dot9r(A2_, wP2, u_);
        u64 z_[9]; load_row(h2b + spo, z_);          // h2[N-2]
        dot9r(A2_, wR2, z_);
        float h2v_ = finish(A2_);
        sts_f32(h2b + slo + 4 * jj, h2v_);
        go2[(size_t)(N - 1) * H_] = h2v_;
    }

    // Final hidden states: segment-3 chains; all finals live in slot (N-1)&1.
    if (write_hidden && sg == 3 && act) {
        const u32 fo = ((N - 1) & 1) * ROWB + 4 * jj;
        out[(size_t)B_ * S_ + 0 * B_ * H_ + b * H_ + lane] = lds_f32(h0b + fo);
        out[(size_t)B_ * S_ + 1 * B_ * H_ + b * H_ + lane] = lds_f32(h1b + fo);
        out[(size_t)B_ * S_ + 2 * B_ * H_ + b * H_ + lane] = lds_f32(h2b + fo);
    }
}

// ---------------------------------------------------------------------------
// Kernel B: MLP head (unchanged from best).
// ---------------------------------------------------------------------------
__global__ __launch_bounds__(256, 5)
void mlp_head_kernel(const float* __restrict__ W1, const float* __restrict__ b1,
                     const float* __restrict__ W2, const float* __restrict__ b2,
                     const float* __restrict__ W3, const float* __restrict__ b3,
                     const float* __restrict__ W4, const float* __restrict__ b4,
                     const float* __restrict__ W5, const float* __restrict__ b5,
                     const float* __restrict__ W6, const float* __restrict__ b6,
                     float* __restrict__ out)
{
    __shared__ u64 sROW[256 * 9];
    __shared__ u64 sW1[162], sW2[90], sW3[40], sW4[16], sW5[4];
    __shared__ float sb1[18], sb2[10], sb3[8], sb4[4], sb5[2], sW6f[2], sb6f[1];

    const int tid = threadIdx.x;
    if (tid < 162) sW1[tid] = __ldg((const u64*)W1 + tid);
    if (tid < 90)  sW2[tid] = __ldg((const u64*)W2 + tid);
    if (tid < 40)  sW3[tid] = __ldg((const u64*)W3 + tid);
    if (tid < 16)  sW4[tid] = __ldg((const u64*)W4 + tid);
    if (tid < 4)  { sW5[tid] = __ldg((const u64*)W5 + tid); sb4[tid] = b4[tid]; }
    if (tid < 18)  sb1[tid] = b1[tid];
    if (tid < 10)  sb2[tid] = b2[tid];
    if (tid < 8)   sb3[tid] = b3[tid];
    if (tid < 2)  { sb5[tid] = b5[tid]; sW6f[tid] = W6[tid]; }
    if (tid == 0)  sb6f[0] = b6[0];

    const size_t base = (size_t)blockIdx.x * 256;
    const u64* gh = (const u64*)g_h2 + base * 9;
    #pragma unroll
    for (int i = 0; i < 9; ++i) sROW[tid + i * 256] = __ldg(&gh[tid + i * 256]);
    __syncthreads();

    u64 a0[9];
    #pragma unroll
    for (int m = 0; m < 9; ++m) a0[m] = sROW[tid * 9 + m];

    float a1[18];
    #pragma unroll
    for (int j = 0; j < 18; ++j) {
        u64 acc = pack2(sb1[j], 0.f), accb = 0ull;
        #pragma unroll
        for (int m = 0; m < 9; ++m) fma2((m & 1) ? accb : acc, sW1[j * 9 + m], a0[m]);
        a1[j] = fmaxf(hsum2(add2(acc, accb)), 0.f);
    }
    u64 a1p[9];
    #pragma unroll
    for (int m = 0; m < 9; ++m) a1p[m] = pack2(a1[2 * m], a1[2 * m + 1]);

    float a2[10];
    #pragma unroll
    for (int j = 0; j < 10; ++j) {
        u64 acc = pack2(sb2[j], 0.f), accb = 0ull;
        #pragma unroll
        for (int m = 0; m < 9; ++m) fma2((m & 1) ? accb : acc, sW2[j * 9 + m], a1p[m]);
        a2[j] = fmaxf(hsum2(add2(acc, accb)), 0.f);
    }
    u64 a2p[5];
    #pragma unroll
    for (int m = 0; m < 5; ++m) a2p[m] = pack2(a2[2 * m], a2[2 * m + 1]);

    float a3[8];
    #pragma unroll
    for (int j = 0; j < 8; ++j) {
        u64 acc = pack2(sb3[j], 0.f), accb = 0ull;
        #pragma unroll
        for (int m = 0; m < 5; ++m) fma2((m & 1) ? accb : acc, sW3[j * 5 + m], a2p[m]);
        a3[j] = fmaxf(hsum2(add2(acc, accb)), 0.f);
    }
    u64 a3p[4];
    #pragma unroll
    for (int m = 0; m < 4; ++m) a3p[m] = pack2(a3[2 * m], a3[2 * m + 1]);

    float a4[4];
    #pragma unroll
    for (int j = 0; j < 4; ++j) {
        u64 acc = pack2(sb4[j], 0.f), accb = 0ull;
        #pragma unroll
        for (int m = 0; m < 4; ++m) fma2((m & 1) ? accb : acc, sW4[j * 4 + m], a3p[m]);
        a4[j] = fmaxf(hsum2(add2(acc, accb)), 0.f);
    }
    u64 a4p[2] = { pack2(a4[0], a4[1]), pack2(a4[2], a4[3]) };

    float a5[2];
    #pragma unroll
    for (int j = 0; j < 2; ++j) {
        u64 acc = pack2(sb5[j], 0.f);
        fma2(acc, sW5[j * 2 + 0], a4p[0]);
        fma2(acc, sW5[j * 2 + 1], a4p[1]);
        a5[j] = fmaxf(hsum2(acc), 0.f);
    }
    out[base + tid] = fmaf(a5[0], sW6f[0], fmaf(a5[1], sW6f[1], sb6f[0]));
}

// ---------------------------------------------------------------------------
// Launch
// ---------------------------------------------------------------------------
extern "C" void kernel_launch(void* const* d_in, const int* in_sizes, int n_in,
                              void* d_out, int out_size)
{
    const float* input  = (const float*)d_in[0];
    const float* hidden = (const float*)d_in[1];
    const float* Wih0 = (const float*)d_in[2];
    const float* bih0 = (const float*)d_in[3];
    const float* Whh0 = (const float*)d_in[4];
    const float* bhh0 = (const float*)d_in[5];
    const float* Wih1 = (const float*)d_in[6];
    const float* bih1 = (const float*)d_in[7];
    const float* Whh1 = (const float*)d_in[8];
    const float* bhh1 = (const float*)d_in[9];
    const float* Wih2 = (const float*)d_in[10];
    const float* bih2 = (const float*)d_in[11];
    const float* Whh2 = (const float*)d_in[12];
    const float* bhh2 = (const float*)d_in[13];
    const float* W1 = (const float*)d_in[14];
    const float* b1 = (const float*)d_in[15];
    const float* W2 = (const float*)d_in[16];
    const float* b2 = (const float*)d_in[17];
    const float* W3 = (const float*)d_in[18];
    const float* b3 = (const float*)d_in[19];
    const float* W4 = (const float*)d_in[20];
    const float* b4 = (const float*)d_in[21];
    const float* W5 = (const float*)d_in[22];
    const float* b5 = (const float*)d_in[23];
    const float* W6 = (const float*)d_in[24];
    const float* b6 = (const float*)d_in[25];

    float* out = (float*)d_out;
    const int write_hidden = (out_size >= B_ * S_ + 3 * B_ * H_) ? 1 : 0;

    xw0_kernel<<<(B_ * S_) / 128, 128>>>(input, Wih0, bih0, bhh0);

    rnn_scan_kernel<<<B_ / 2, 256>>>(hidden, Whh0,
                                     Wih1, bih1, Whh1, bhh1,
                                     Wih2, bih2, Whh2, bhh2,
                                     out, write_hidden);

    mlp_head_kernel<<<(B_ * S_) / 256, 256>>>(W1, b1, W2, b2, W3, b3,
                                              W4, b4, W5, b5, W6, b6, out);
}

// round 16
// speedup vs baseline: 1.3741x; 1.1172x over previous
#include <cuda_runtime.h>
#include <math.h>

typedef unsigned long long u64;
typedef unsigned int u32;

// Problem dims
#define B_  256
#define S_  2048
#define I_  32
#define H_  18

// Fused-scan config: 4 temporal segments, 1 warp per chain (3 layers skewed).
#define NSEG    4
#define SEGSTEP (S_ / NSEG)      // 512 new steps per segment
#define BURN    128              // burn-in steps (segments 1..3)
#define RS2     10               // ring row stride in u64 (80 bytes)
#define ROWB    80

// Scratch
__device__ float g_h2[(size_t)B_ * S_ * H_];   // layer-2 hidden sequence
__device__ float g_xw[(size_t)B_ * S_ * H_];   // Wih0·x + bih0 + bhh0

// ---------------- packed f32x2 helpers ----------------
__device__ __forceinline__ void fma2(u64& d, u64 a, u64 b) {
    asm("fma.rn.f32x2 %0, %1, %2, %0;" : "+l"(d) : "l"(a), "l"(b));
}
__device__ __forceinline__ u64 add2(u64 a, u64 b) {
    u64 d; asm("add.rn.f32x2 %0, %1, %2;" : "=l"(d) : "l"(a), "l"(b)); return d;
}
__device__ __forceinline__ float hsum2(u64 a) {
    float x, y; asm("mov.b64 {%0, %1}, %2;" : "=f"(x), "=f"(y) : "l"(a));
    return x + y;
}
__device__ __forceinline__ u64 pack2(float x, float y) {
    u64 d; asm("mov.b64 %0, {%1, %2};" : "=l"(d) : "f"(x), "f"(y)); return d;
}
__device__ __forceinline__ float tanh_fast(float x) {
    float r; asm("tanh.approx.f32 %0, %1;" : "=f"(r) : "f"(x)); return r;
}
// Ordered shared ops (same-warp in-order smem pipe; volatile pins order).
__device__ __forceinline__ void sts_f32(u32 addr, float v) {
    asm volatile("st.shared.f32 [%0], %1;" :: "r"(addr), "f"(v));
}
__device__ __forceinline__ u64 lds_u64(u32 addr) {
    u64 v; asm volatile("ld.shared.b64 %0, [%1];" : "=l"(v) : "r"(addr)); return v;
}
__device__ __forceinline__ void lds_pair(u32 addr, u64& x, u64& y) {
    asm volatile("ld.shared.v2.b64 {%0,%1}, [%2];" : "=l"(x), "=l"(y) : "r"(addr));
}
__device__ __forceinline__ float lds_f32(u32 addr) {
    float v; asm volatile("ld.shared.f32 %0, [%1];" : "=f"(v) : "r"(addr)); return v;
}

struct Acc { u64 a0, a1, a2; };

__device__ __forceinline__ void load_row(u32 a, u64* v) {
    lds_pair(a,      v[0], v[1]);
    lds_pair(a + 16, v[2], v[3]);
    lds_pair(a + 32, v[4], v[5]);
    lds_pair(a + 48, v[6], v[7]);
    v[8] = lds_u64(a + 64);
}
__device__ __forceinline__ void dot9r(Acc& A, const u64* w, const u64* v) {
    fma2(A.a0, w[0], v[0]); fma2(A.a1, w[1], v[1]); fma2(A.a2, w[2], v[2]);
    fma2(A.a0, w[3], v[3]); fma2(A.a1, w[4], v[4]); fma2(A.a2, w[5], v[5]);
    fma2(A.a0, w[6], v[6]); fma2(A.a1, w[7], v[7]); fma2(A.a2, w[8], v[8]);
}
__device__ __forceinline__ float finish(Acc& A) {
    return tanh_fast(hsum2(add2(add2(A.a0, A.a1), A.a2)));
}

// ---------------------------------------------------------------------------
// Kernel 0: g_xw[b,t,:] = Wih0 · x[b,t,:] + bih0 + bhh0.
// Fully coalesced: stage 128 rows (pad-17 u64 stride -> 2-way LDS conflicts),
// compute per-thread row, pack pairs, write back coalesced.
// ---------------------------------------------------------------------------
__global__ __launch_bounds__(128)
void xw0_kernel(const float* __restrict__ input,
                const float* __restrict__ Wih0,
                const float* __restrict__ bih0,
                const float* __restrict__ bhh0)
{
    __shared__ u64 sW[288];              // 18x32 f as u64 pairs
    __shared__ float sB[18];
    __shared__ u64 sIN[128 * 17];        // 128 rows x 16 u64, pad stride 17
    __shared__ u64 sOut[128 * 9];        // 128 rows x 18 f

    const int tid = threadIdx.x;
    sW[tid] = __ldg((const u64*)Wih0 + tid);
    sW[tid + 128] = __ldg((const u64*)Wih0 + tid + 128);
    if (tid < 32) sW[tid + 256] = __ldg((const u64*)Wih0 + tid + 256);
    if (tid < 18) sB[tid] = __ldg(&bih0[tid]) + __ldg(&bhh0[tid]);

    // Coalesced stage of 128 rows (2048 u64 contiguous), scattered to pad-17.
    const u64* gx = (const u64*)input + (size_t)blockIdx.x * 2048;
    #pragma unroll
    for (int i = 0; i < 16; ++i) {
        const int g = tid + 128 * i;
        sIN[(g >> 4) * 17 + (g & 15)] = __ldg(&gx[g]);
    }
    __syncthreads();

    u64 xv[16];
    #pragma unroll
    for (int m = 0; m < 16; ++m) xv[m] = sIN[tid * 17 + m];

    // 18 outputs, packed into 9 u64 (same FMA order as before -> bit-exact).
    #pragma unroll
    for (int jp = 0; jp < 9; ++jp) {
        float o[2];
        #pragma unroll
        for (int e = 0; e < 2; ++e) {
            const int j = 2 * jp + e;
            u64 acc = pack2(sB[j], 0.f), accb = 0ull;
            #pragma unroll
            for (int m = 0; m < 16; ++m)
                fma2((m & 1) ? accb : acc, sW[j * 16 + m], xv[m]);
            o[e] = hsum2(add2(acc, accb));
        }
        sOut[tid * 9 + jp] = pack2(o[0], o[1]);
    }
    __syncthreads();

    u64* go = (u64*)g_xw + (size_t)blockIdx.x * (128 * 9);
    #pragma unroll
    for (int k2 = 0; k2 < 9; ++k2) go[tid + k2 * 128] = sOut[tid + k2 * 128];
}

// ---------------------------------------------------------------------------
// Kernel A: fused 3-layer RNN scan, one warp per chain, layers time-skewed:
// at iteration i the warp computes h0[i], h1[i-1], h2[i-2].
// Depth-2 rings, all intra-warp (volatile order), ZERO barriers.
// Block: 8 warps = 8 chains (2 batches x 4 segments). Grid 128 = one wave.
// ---------------------------------------------------------------------------
#define FSTEP(I, DO_L1, DO_L2, XWV) do {                                      \
    const u32 slo = ((I) & 1) * ROWB, spo = slo ^ ROWB;                       \
    u64 v_[9];                                                                \
    load_row(h0b + spo, v_);                    /* h0[i-1] */                 \
    Acc A0_ = { pack2((XWV), 0.f), 0ull, 0ull };                              \
    dot9r(A0_, wR0, v_);                                                      \
    Acc A1_ = { b1init, 0ull, 0ull };                                         \
    if (DO_L1) dot9r(A1_, wP1, v_);                                           \
    u64 u_[9];                                                                \
    if (DO_L1 || DO_L2) load_row(h1b + slo, u_); /* h1[i-2] */                \
    if (DO_L1) dot9r(A1_, wR1, u_);                                           \
    Acc A2_ = { b2init, 0ull, 0ull };                                         \
    if (DO_L2) {                                                              \
        dot9r(A2_, wP2, u_);                                                  \
        u64 z_[9];                                                            \
        load_row(h2b + spo, z_);                /* h2[i-3] */                 \
        dot9r(A2_, wR2, z_);                                                  \
    }                                                                         \
    float h0v_ = finish(A0_);                                                 \
    sts_f32(h0b + slo + 4 * jj, h0v_);                                        \
    if (DO_L1) {                                                              \
        float h1v_ = finish(A1_);                                             \
        sts_f32(h1b + spo + 4 * jj, h1v_);                                    \
    }                                                                         \
    if (DO_L2) {                                                              \
        float h2v_ = finish(A2_);                                             \
        sts_f32(h2b + slo + 4 * jj, h2v_);                                    \
        if ((I) >= wstart) go2[(size_t)((I) - 2) * H_] = h2v_;                \
    }                                                                         \
} while (0)

__global__ __launch_bounds__(256, 1)
void rnn_scan_kernel(const float* __restrict__ hidden,
                     const float* __restrict__ Whh0,
                     const float* __restrict__ Wih1, const float* __restrict__ bih1,
                     const float* __restrict__ Whh1, const float* __restrict__ bhh1,
                     const float* __restrict__ Wih2, const float* __restrict__ bih2,
                     const float* __restrict__ Whh2, const float* __restrict__ bhh2,
                     float* __restrict__ out, int write_hidden)
{
    __shared__ __align__(16) u64 s_h[8][3][2][RS2];   // per-chain depth-2 rings

    const int tid  = threadIdx.x;
    const int w    = tid >> 5;                // chain index 0..7
    const int lane = tid & 31;
    const int bi   = w & 1;
    const int sg   = w >> 1;                  // segment 0..3
    const int b    = blockIdx.x * 2 + bi;
    const int jj   = (lane < H_) ? lane : 0;  // clamped; dup lanes benign
    const bool act = (lane < H_);

    const int base_t = sg ? (sg * SEGSTEP - BURN) : 0;
    const int N      = sg ? (SEGSTEP + BURN) : SEGSTEP;   // 640 / 512
    const int wstart = sg ? (BURN + 2) : 2;               // first STG iteration

    u64 wR0[9], wP1[9], wR1[9], wP2[9], wR2[9];
    {
        const u64* p0 = (const u64*)(Whh0 + jj * H_);
        const u64* p1 = (const u64*)(Wih1 + jj * H_);
        const u64* p2 = (const u64*)(Whh1 + jj * H_);
        const u64* p3 = (const u64*)(Wih2 + jj * H_);
        const u64* p4 = (const u64*)(Whh2 + jj * H_);
        #pragma unroll
        for (int m = 0; m < 9; ++m) {
            wR0[m] = __ldg(&p0[m]); wP1[m] = __ldg(&p1[m]); wR1[m] = __ldg(&p2[m]);
            wP2[m] = __ldg(&p3[m]); wR2[m] = __ldg(&p4[m]);
        }
    }
    const u64 b1init = pack2(__ldg(&bih1[jj]) + __ldg(&bhh1[jj]), 0.f);
    const u64 b2init = pack2(__ldg(&bih2[jj]) + __ldg(&bhh2[jj]), 0.f);

    const u32 h0b = (u32)__cvta_generic_to_shared(&s_h[w][0][0][0]);
    const u32 h1b = (u32)__cvta_generic_to_shared(&s_h[w][1][0][0]);
    const u32 h2b = (u32)__cvta_generic_to_shared(&s_h[w][2][0][0]);

    // Seeds into slot 1 of each ring.
    {
        float h0i = sg ? 0.f : __ldg(&hidden[0 * B_ * H_ + b * H_ + jj]);
        float h1i = sg ? 0.f : __ldg(&hidden[1 * B_ * H_ + b * H_ + jj]);
        float h2i = sg ? 0.f : __ldg(&hidden[2 * B_ * H_ + b * H_ + jj]);
        sts_f32(h0b + ROWB + 4 * jj, h0i);
        sts_f32(h1b + ROWB + 4 * jj, h1i);
        sts_f32(h2b + ROWB + 4 * jj, h2i);
    }

    const float* xwp = g_xw + ((size_t)b * S_ + base_t) * H_ + jj;
    float* go2 = g_h2 + ((size_t)b * S_ + base_t) * H_ + jj;

    float xcur[8], xnxt[8];
    #pragma unroll
    for (int u = 0; u < 8; ++u) xcur[u] = __ldg(&xwp[u * H_]);
    xwp += 8 * H_;

    const int nch = N >> 3;

    // ---- chunk 0 (i=0..7): pipe fill, guarded ----
    {
        #pragma unroll
        for (int u = 0; u < 8; ++u) xnxt[u] = __ldg(&xwp[u * H_]);
        xwp += 8 * H_;
        FSTEP(0, false, false, xcur[0]);
        FSTEP(1, true,  false, xcur[1]);
        FSTEP(2, true,  true,  xcur[2]);
        FSTEP(3, true,  true,  xcur[3]);
        FSTEP(4, true,  true,  xcur[4]);
        FSTEP(5, true,  true,  xcur[5]);
        FSTEP(6, true,  true,  xcur[6]);
        FSTEP(7, true,  true,  xcur[7]);
        #pragma unroll
        for (int u = 0; u < 8; ++u) xcur[u] = xnxt[u];
    }

    // ---- steady chunks ----
    for (int c = 1; c < nch; ++c) {
        const bool pf = (c + 1) < nch;
        if (pf) {
            #pragma unroll
            for (int u = 0; u < 8; ++u) xnxt[u] = __ldg(&xwp[u * H_]);
            xwp += 8 * H_;
        }
        const int i0 = c * 8;
        #pragma unroll
        for (int u = 0; u < 8; ++u) {
            FSTEP(i0 + u, true, true, xcur[u]);
        }
        if (pf) {
            #pragma unroll
            for (int u = 0; u < 8; ++u) xcur[u] = xnxt[u];
        }
    }

    // ---- epilogue: i = N (L1+L2), i = N+1 (L2) ----
    {
        const u32 slo = (N & 1) * ROWB, spo = slo ^ ROWB;
        u64 v_[9]; load_row(h0b + spo, v_);          // h0[N-1]
        Acc A1_ = { b1init, 0ull, 0ull };
        dot9r(A1_, wP1, v_);
        u64 u_[9]; load_row(h1b + slo, u_);          // h1[N-2]
        dot9r(A1_, wR1, u_);
        Acc A2_ = { b2init, 0ull, 0ull };
        dot9r(A2_, wP2, u_);
        u64 z_[9]; load_row(h2b + spo, z_);          // h2[N-3]
        dot9r(A2_, wR2, z_);
        float h1v_ = finish(A1_);
        sts_f32(h1b + spo + 4 * jj, h1v_);
        float h2v_ = finish(A2_);
        sts_f32(h2b + slo + 4 * jj, h2v_);
        go2[(size_t)(N - 2) * H_] = h2v_;
    }
    {
        const u32 slo = ((N + 1) & 1) * ROWB, spo = slo ^ ROWB;
        u64 u_[9]; load_row(h1b + slo, u_);          // h1[N-1]
        Acc A2_ = { b2init, 0ull, 0ull };
        dot9r(A2_, wP2, u_);
        u64 z_[9]; load_row(h2b + spo, z_);          // h2[N-2]
        dot9r(A2_, wR2, z_);
        float h2v_ = finish(A2_);
        sts_f32(h2b + slo + 4 * jj, h2v_);
        go2[(size_t)(N - 1) * H_] = h2v_;
    }

    if (write_hidden && sg == 3 && act) {
        const u32 fo = ((N - 1) & 1) * ROWB + 4 * jj;
        out[(size_t)B_ * S_ + 0 * B_ * H_ + b * H_ + lane] = lds_f32(h0b + fo);
        out[(size_t)B_ * S_ + 1 * B_ * H_ + b * H_ + lane] = lds_f32(h1b + fo);
        out[(size_t)B_ * S_ + 2 * B_ * H_ + b * H_ + lane] = lds_f32(h2b + fo);
    }
}

// ---------------------------------------------------------------------------
// Kernel B: MLP head (unchanged from best).
// ---------------------------------------------------------------------------
__global__ __launch_bounds__(256, 5)
void mlp_head_kernel(const float* __restrict__ W1, const float* __restrict__ b1,
                     const float* __restrict__ W2, const float* __restrict__ b2,
                     const float* __restrict__ W3, const float* __restrict__ b3,
                     const float* __restrict__ W4, const float* __restrict__ b4,
                     const float* __restrict__ W5, const float* __restrict__ b5,
                     const float* __restrict__ W6, const float* __restrict__ b6,
                     float* __restrict__ out)
{
    __shared__ u64 sROW[256 * 9];
    __shared__ u64 sW1[162], sW2[90], sW3[40], sW4[16], sW5[4];
    __shared__ float sb1[18], sb2[10], sb3[8], sb4[4], sb5[2], sW6f[2], sb6f[1];

    const int tid = threadIdx.x;
    if (tid < 162) sW1[tid] = __ldg((const u64*)W1 + tid);
    if (tid < 90)  sW2[tid] = __ldg((const u64*)W2 + tid);
    if (tid < 40)  sW3[tid] = __ldg((const u64*)W3 + tid);
    if (tid < 16)  sW4[tid] = __ldg((const u64*)W4 + tid);
    if (tid < 4)  { sW5[tid] = __ldg((const u64*)W5 + tid); sb4[tid] = b4[tid]; }
    if (tid < 18)  sb1[tid] = b1[tid];
    if (tid < 10)  sb2[tid] = b2[tid];
    if (tid < 8)   sb3[tid] = b3[tid];
    if (tid < 2)  { sb5[tid] = b5[tid]; sW6f[tid] = W6[tid]; }
    if (tid == 0)  sb6f[0] = b6[0];

    const size_t base = (size_t)blockIdx.x * 256;
    const u64* gh = (const u64*)g_h2 + base * 9;
    #pragma unroll
    for (int i = 0; i < 9; ++i) sROW[tid + i * 256] = __ldg(&gh[tid + i * 256]);
    __syncthreads();

    u64 a0[9];
    #pragma unroll
    for (int m = 0; m < 9; ++m) a0[m] = sROW[tid * 9 + m];

    float a1[18];
    #pragma unroll
    for (int j = 0; j < 18; ++j) {
        u64 acc = pack2(sb1[j], 0.f), accb = 0ull;
        #pragma unroll
        for (int m = 0; m < 9; ++m) fma2((m & 1) ? accb : acc, sW1[j * 9 + m], a0[m]);
        a1[j] = fmaxf(hsum2(add2(acc, accb)), 0.f);
    }
    u64 a1p[9];
    #pragma unroll
    for (int m = 0; m < 9; ++m) a1p[m] = pack2(a1[2 * m], a1[2 * m + 1]);

    float a2[10];
    #pragma unroll
    for (int j = 0; j < 10; ++j) {
        u64 acc = pack2(sb2[j], 0.f), accb = 0ull;
        #pragma unroll
        for (int m = 0; m < 9; ++m) fma2((m & 1) ? accb : acc, sW2[j * 9 + m], a1p[m]);
        a2[j] = fmaxf(hsum2(add2(acc, accb)), 0.f);
    }
    u64 a2p[5];
    #pragma unroll
    for (int m = 0; m < 5; ++m) a2p[m] = pack2(a2[2 * m], a2[2 * m + 1]);

    float a3[8];
    #pragma unroll
    for (int j = 0; j < 8; ++j) {
        u64 acc = pack2(sb3[j], 0.f), accb = 0ull;
        #pragma unroll
        for (int m = 0; m < 5; ++m) fma2((m & 1) ? accb : acc, sW3[j * 5 + m], a2p[m]);
        a3[j] = fmaxf(hsum2(add2(acc, accb)), 0.f);
    }
    u64 a3p[4];
    #pragma unroll
    for (int m = 0; m < 4; ++m) a3p[m] = pack2(a3[2 * m], a3[2 * m + 1]);

    float a4[4];
    #pragma unroll
    for (int j = 0; j < 4; ++j) {
        u64 acc = pack2(sb4[j], 0.f), accb = 0ull;
        #pragma unroll
        for (int m = 0; m < 4; ++m) fma2((m & 1) ? accb : acc, sW4[j * 4 + m], a3p[m]);
        a4[j] = fmaxf(hsum2(add2(acc, accb)), 0.f);
    }
    u64 a4p[2] = { pack2(a4[0], a4[1]), pack2(a4[2], a4[3]) };

    float a5[2];
    #pragma unroll
    for (int j = 0; j < 2; ++j) {
        u64 acc = pack2(sb5[j], 0.f);
        fma2(acc, sW5[j * 2 + 0], a4p[0]);
        fma2(acc, sW5[j * 2 + 1], a4p[1]);
        a5[j] = fmaxf(hsum2(acc), 0.f);
    }
    out[base + tid] = fmaf(a5[0], sW6f[0], fmaf(a5[1], sW6f[1], sb6f[0]));
}

// ---------------------------------------------------------------------------
// Launch
// ---------------------------------------------------------------------------
extern "C" void kernel_launch(void* const* d_in, const int* in_sizes, int n_in,
                              void* d_out, int out_size)
{
    const float* input  = (const float*)d_in[0];
    const float* hidden = (const float*)d_in[1];
    const float* Wih0 = (const float*)d_in[2];
    const float* bih0 = (const float*)d_in[3];
    const float* Whh0 = (const float*)d_in[4];
    const float* bhh0 = (const float*)d_in[5];
    const float* Wih1 = (const float*)d_in[6];
    const float* bih1 = (const float*)d_in[7];
    const float* Whh1 = (const float*)d_in[8];
    const float* bhh1 = (const float*)d_in[9];
    const float* Wih2 = (const float*)d_in[10];
    const float* bih2 = (const float*)d_in[11];
    const float* Whh2 = (const float*)d_in[12];
    const float* bhh2 = (const float*)d_in[13];
    const float* W1 = (const float*)d_in[14];
    const float* b1 = (const float*)d_in[15];
    const float* W2 = (const float*)d_in[16];
    const float* b2 = (const float*)d_in[17];
    const float* W3 = (const float*)d_in[18];
    const float* b3 = (const float*)d_in[19];
    const float* W4 = (const float*)d_in[20];
    const float* b4 = (const float*)d_in[21];
    const float* W5 = (const float*)d_in[22];
    const float* b5 = (const float*)d_in[23];
    const float* W6 = (const float*)d_in[24];
    const float* b6 = (const float*)d_in[25];

    float* out = (float*)d_out;
    const int write_hidden = (out_size >= B_ * S_ + 3 * B_ * H_) ? 1 : 0;

    xw0_kernel<<<(B_ * S_) / 128, 128>>>(input, Wih0, bih0, bhh0);

    rnn_scan_kernel<<<B_ / 2, 256>>>(hidden, Whh0,
                                     Wih1, bih1, Whh1, bhh1,
                                     Wih2, bih2, Whh2, bhh2,
                                     out, write_hidden);

    mlp_head_kernel<<<(B_ * S_) / 256, 256>>>(W1, b1, W2, b2, W3, b3,
                                              W4, b4, W5, b5, W6, b6, out);
}

// round 17
// speedup vs baseline: 1.4537x; 1.0580x over previous
#include <cuda_runtime.h>
#include <math.h>

typedef unsigned long long u64;
typedef unsigned int u32;

// Problem dims
#define B_  256
#define S_  2048
#define I_  32
#define H_  18

// Fused-scan config: 4 temporal segments, 1 warp per chain (3 layers skewed).
#define NSEG    4
#define SEGSTEP (S_ / NSEG)      // 512 new steps per segment
#define BURN    128              // burn-in steps (segments 1..3)
#define RS2     10               // row stride in u64 (80 bytes)

// Scratch
__device__ float g_h2[(size_t)B_ * S_ * H_];   // layer-2 hidden sequence
__device__ float g_xw[(size_t)B_ * S_ * H_];   // Wih0·x + bih0 + bhh0

// ---------------- packed f32x2 helpers ----------------
__device__ __forceinline__ void fma2(u64& d, u64 a, u64 b) {
    asm("fma.rn.f32x2 %0, %1, %2, %0;" : "+l"(d) : "l"(a), "l"(b));
}
__device__ __forceinline__ u64 add2(u64 a, u64 b) {
    u64 d; asm("add.rn.f32x2 %0, %1, %2;" : "=l"(d) : "l"(a), "l"(b)); return d;
}
__device__ __forceinline__ float hsum2(u64 a) {
    float x, y; asm("mov.b64 {%0, %1}, %2;" : "=f"(x), "=f"(y) : "l"(a));
    return x + y;
}
__device__ __forceinline__ u64 pack2(float x, float y) {
    u64 d; asm("mov.b64 %0, {%1, %2};" : "=l"(d) : "f"(x), "f"(y)); return d;
}
__device__ __forceinline__ float tanh_fast(float x) {
    float r; asm("tanh.approx.f32 %0, %1;" : "=f"(r) : "f"(x)); return r;
}
// Ordered shared ops (same-warp in-order smem pipe; volatile pins order).
__device__ __forceinline__ void sts_f32(u32 addr, float v) {
    asm volatile("st.shared.f32 [%0], %1;" :: "r"(addr), "f"(v));
}
__device__ __forceinline__ u64 lds_u64(u32 addr) {
    u64 v; asm volatile("ld.shared.b64 %0, [%1];" : "=l"(v) : "r"(addr)); return v;
}
__device__ __forceinline__ void lds_pair(u32 addr, u64& x, u64& y) {
    asm volatile("ld.shared.v2.b64 {%0,%1}, [%2];" : "=l"(x), "=l"(y) : "r"(addr));
}

struct Acc { u64 a0, a1, a2; };

__device__ __forceinline__ void load_row(u32 a, u64* v) {
    lds_pair(a,      v[0], v[1]);
    lds_pair(a + 16, v[2], v[3]);
    lds_pair(a + 32, v[4], v[5]);
    lds_pair(a + 48, v[6], v[7]);
    v[8] = lds_u64(a + 64);
}
__device__ __forceinline__ void dot9r(Acc& A, const u64* w, const u64* v) {
    fma2(A.a0, w[0], v[0]); fma2(A.a1, w[1], v[1]); fma2(A.a2, w[2], v[2]);
    fma2(A.a0, w[3], v[3]); fma2(A.a1, w[4], v[4]); fma2(A.a2, w[5], v[5]);
    fma2(A.a0, w[6], v[6]); fma2(A.a1, w[7], v[7]); fma2(A.a2, w[8], v[8]);
}
__device__ __forceinline__ float finish(Acc& A) {
    return tanh_fast(hsum2(add2(add2(A.a0, A.a1), A.a2)));
}

// ---------------------------------------------------------------------------
// Kernel 0: g_xw[b,t,:] = Wih0 · x[b,t,:] + bih0 + bhh0.  (unchanged, proven)
// ---------------------------------------------------------------------------
__global__ __launch_bounds__(128)
void xw0_kernel(const float* __restrict__ input,
                const float* __restrict__ Wih0,
                const float* __restrict__ bih0,
                const float* __restrict__ bhh0)
{
    __shared__ u64 sW[288];
    __shared__ float sB[18];
    __shared__ u64 sIN[128 * 17];
    __shared__ u64 sOut[128 * 9];

    const int tid = threadIdx.x;
    sW[tid] = __ldg((const u64*)Wih0 + tid);
    sW[tid + 128] = __ldg((const u64*)Wih0 + tid + 128);
    if (tid < 32) sW[tid + 256] = __ldg((const u64*)Wih0 + tid + 256);
    if (tid < 18) sB[tid] = __ldg(&bih0[tid]) + __ldg(&bhh0[tid]);

    const u64* gx = (const u64*)input + (size_t)blockIdx.x * 2048;
    #pragma unroll
    for (int i = 0; i < 16; ++i) {
        const int g = tid + 128 * i;
        sIN[(g >> 4) * 17 + (g & 15)] = __ldg(&gx[g]);
    }
    __syncthreads();

    u64 xv[16];
    #pragma unroll
    for (int m = 0; m < 16; ++m) xv[m] = sIN[tid * 17 + m];

    #pragma unroll
    for (int jp = 0; jp < 9; ++jp) {
        float o[2];
        #pragma unroll
        for (int e = 0; e < 2; ++e) {
            const int j = 2 * jp + e;
            u64 acc = pack2(sB[j], 0.f), accb = 0ull;
            #pragma unroll
            for (int m = 0; m < 16; ++m)
                fma2((m & 1) ? accb : acc, sW[j * 16 + m], xv[m]);
            o[e] = hsum2(add2(acc, accb));
        }
        sOut[tid * 9 + jp] = pack2(o[0], o[1]);
    }
    __syncthreads();

    u64* go = (u64*)g_xw + (size_t)blockIdx.x * (128 * 9);
    #pragma unroll
    for (int k2 = 0; k2 < 9; ++k2) go[tid + k2 * 128] = sOut[tid + k2 * 128];
}

// ---------------------------------------------------------------------------
// Kernel A: fused 3-layer scan, SOFTWARE-PIPELINED.
// Rows register-resident (v=h0[i-1], u=h1[i-2], z=h2[i-3]); each layer:
// dot(regs) -> tanh -> STS row -> reload row into regs (single 80B slot,
// in-order smem pipe). The h0 recurrence closes in ~90cyc while L1/L2 issue
// in its shadow (their results consumed one step later).
// Block: 8 warps = 8 chains (2 batches x 4 segments). Grid 128 = one wave.
// ---------------------------------------------------------------------------
#define PSTEP(I, DO_L1, DO_L2, XWV) do {                                      \
    Acc A0_ = { pack2((XWV), 0.f), 0ull, 0ull };                              \
    dot9r(A0_, wR0, v);                                                       \
    h0last = finish(A0_);                                                     \
    sts_f32(h0b + 4 * jj, h0last);                                            \
    Acc A1_ = { b1init, 0ull, 0ull };                                         \
    if (DO_L1) dot9r(A1_, wP1, v);                                            \
    load_row(h0b, v);                       /* v <- h0[i] */                  \
    if (DO_L1) {                                                              \
        dot9r(A1_, wR1, u);                                                   \
        h1last = finish(A1_);                                                 \
        sts_f32(h1b + 4 * jj, h1last);                                        \
    }                                                                         \
    if (DO_L2) {                                                              \
        Acc A2_ = { b2init, 0ull, 0ull };                                     \
        dot9r(A2_, wP2, u);                                                   \
        load_row(h1b, u);                   /* u <- h1[i-1] */                \
        dot9r(A2_, wR2, z);                                                   \
        h2last = finish(A2_);                                                 \
        sts_f32(h2b + 4 * jj, h2last);                                        \
        load_row(h2b, z);                   /* z <- h2[i-2] */                \
        if ((I) >= wstart) go2[(size_t)((I) - 2) * H_] = h2last;              \
    } else if (DO_L1) {                                                       \
        load_row(h1b, u);                                                     \
    }                                                                         \
} while (0)

__global__ __launch_bounds__(256, 1)
void rnn_scan_kernel(const float* __restrict__ hidden,
                     const float* __restrict__ Whh0,
                     const float* __restrict__ Wih1, const float* __restrict__ bih1,
                     const float* __restrict__ Whh1, const float* __restrict__ bhh1,
                     const float* __restrict__ Wih2, const float* __restrict__ bih2,
                     const float* __restrict__ Whh2, const float* __restrict__ bhh2,
                     float* __restrict__ out, int write_hidden)
{
    __shared__ __align__(16) u64 s_row[8][3][RS2];   // one 80B row per layer/chain

    const int tid  = threadIdx.x;
    const int w    = tid >> 5;                // chain index 0..7
    const int lane = tid & 31;
    const int bi   = w & 1;
    const int sg   = w >> 1;                  // segment 0..3
    const int b    = blockIdx.x * 2 + bi;
    const int jj   = (lane < H_) ? lane : 0;  // clamped; dup lanes benign
    const bool act = (lane < H_);

    const int base_t = sg ? (sg * SEGSTEP - BURN) : 0;
    const int N      = sg ? (SEGSTEP + BURN) : SEGSTEP;   // 640 / 512
    const int wstart = sg ? (BURN + 2) : 2;               // first STG iteration

    u64 wR0[9], wP1[9], wR1[9], wP2[9], wR2[9];
    {
        const u64* p0 = (const u64*)(Whh0 + jj * H_);
        const u64* p1 = (const u64*)(Wih1 + jj * H_);
        const u64* p2 = (const u64*)(Whh1 + jj * H_);
        const u64* p3 = (const u64*)(Wih2 + jj * H_);
        const u64* p4 = (const u64*)(Whh2 + jj * H_);
        #pragma unroll
        for (int m = 0; m < 9; ++m) {
            wR0[m] = __ldg(&p0[m]); wP1[m] = __ldg(&p1[m]); wR1[m] = __ldg(&p2[m]);
            wP2[m] = __ldg(&p3[m]); wR2[m] = __ldg(&p4[m]);
        }
    }
    const u64 b1init = pack2(__ldg(&bih1[jj]) + __ldg(&bhh1[jj]), 0.f);
    const u64 b2init = pack2(__ldg(&bih2[jj]) + __ldg(&bhh2[jj]), 0.f);

    const u32 h0b = (u32)__cvta_generic_to_shared(&s_row[w][0][0]);
    const u32 h1b = (u32)__cvta_generic_to_shared(&s_row[w][1][0]);
    const u32 h2b = (u32)__cvta_generic_to_shared(&s_row[w][2][0]);

    // Register-resident rows, seeded directly from `hidden` (broadcast LDG;
    // 72B rows are 8B-aligned).
    u64 v[9], u[9], z[9];
    if (sg == 0) {
        const u64* q0 = (const u64*)(hidden + 0 * B_ * H_ + b * H_);
        const u64* q1 = (const u64*)(hidden + 1 * B_ * H_ + b * H_);
        const u64* q2 = (const u64*)(hidden + 2 * B_ * H_ + b * H_);
        #pragma unroll
        for (int m = 0; m < 9; ++m) {
            v[m] = __ldg(&q0[m]); u[m] = __ldg(&q1[m]); z[m] = __ldg(&q2[m]);
        }
    } else {
        #pragma unroll
        for (int m = 0; m < 9; ++m) { v[m] = 0ull; u[m] = 0ull; z[m] = 0ull; }
    }

    const float* xwp = g_xw + ((size_t)b * S_ + base_t) * H_ + jj;
    float* go2 = g_h2 + ((size_t)b * S_ + base_t) * H_ + jj;

    float h0last = 0.f, h1last = 0.f, h2last = 0.f;

    float xcur[8], xnxt[8];
    #pragma unroll
    for (int q = 0; q < 8; ++q) xcur[q] = __ldg(&xwp[q * H_]);
    xwp += 8 * H_;

    const int nch = N >> 3;

    // ---- chunk 0 (i=0..7): pipe fill, guarded ----
    {
        #pragma unroll
        for (int q = 0; q < 8; ++q) xnxt[q] = __ldg(&xwp[q * H_]);
        xwp += 8 * H_;
        PSTEP(0, false, false, xcur[0]);
        PSTEP(1, true,  false, xcur[1]);
        PSTEP(2, true,  true,  xcur[2]);
        PSTEP(3, true,  true,  xcur[3]);
        PSTEP(4, true,  true,  xcur[4]);
        PSTEP(5, true,  true,  xcur[5]);
        PSTEP(6, true,  true,  xcur[6]);
        PSTEP(7, true,  true,  xcur[7]);
        #pragma unroll
        for (int q = 0; q < 8; ++q) xcur[q] = xnxt[q];
    }

    // ---- steady chunks ----
    for (int c = 1; c < nch; ++c) {
        const bool pf = (c + 1) < nch;
        if (pf) {
            #pragma unroll
            for (int q = 0; q < 8; ++q) xnxt[q] = __ldg(&xwp[q * H_]);
            xwp += 8 * H_;
        }
        const int i0 = c * 8;
        #pragma unroll
        for (int q = 0; q < 8; ++q) {
            PSTEP(i0 + q, true, true, xcur[q]);
        }
        if (pf) {
            #pragma unroll
            for (int q = 0; q < 8; ++q) xcur[q] = xnxt[q];
        }
    }

    // ---- epilogue iter N: h1[N-1] and h2[N-2] ----
    {
        Acc A1_ = { b1init, 0ull, 0ull };
        dot9r(A1_, wP1, v);
        dot9r(A1_, wR1, u);
        h1last = finish(A1_);
        sts_f32(h1b + 4 * jj, h1last);
        Acc A2_ = { b2init, 0ull, 0ull };
        dot9r(A2_, wP2, u);
        load_row(h1b, u);                    // u <- h1[N-1]
        dot9r(A2_, wR2, z);
        float h2v_ = finish(A2_);
        sts_f32(h2b + 4 * jj, h2v_);
        load_row(h2b, z);                    // z <- h2[N-2]
        go2[(size_t)(N - 2) * H_] = h2v_;
    }
    // ---- epilogue iter N+1: h2[N-1] ----
    {
        Acc A2_ = { b2init, 0ull, 0ull };
        dot9r(A2_, wP2, u);
        dot9r(A2_, wR2, z);
        h2last = finish(A2_);
        go2[(size_t)(N - 1) * H_] = h2last;
    }

    // Final hidden states from segment-3 chains (register-resident).
    if (write_hidden && sg == 3 && act) {
        out[(size_t)B_ * S_ + 0 * B_ * H_ + b * H_ + lane] = h0last;
        out[(size_t)B_ * S_ + 1 * B_ * H_ + b * H_ + lane] = h1last;
        out[(size_t)B_ * S_ + 2 * B_ * H_ + b * H_ + lane] = h2last;
    }
}

// ---------------------------------------------------------------------------
// Kernel B: MLP head (unchanged from best).
// ---------------------------------------------------------------------------
__global__ __launch_bounds__(256, 5)
void mlp_head_kernel(const float* __restrict__ W1, const float* __restrict__ b1,
                     const float* __restrict__ W2, const float* __restrict__ b2,
                     const float* __restrict__ W3, const float* __restrict__ b3,
                     const float* __restrict__ W4, const float* __restrict__ b4,
                     const float* __restrict__ W5, const float* __restrict__ b5,
                     const float* __restrict__ W6, const float* __restrict__ b6,
                     float* __restrict__ out)
{
    __shared__ u64 sROW[256 * 9];
    __shared__ u64 sW1[162], sW2[90], sW3[40], sW4[16], sW5[4];
    __shared__ float sb1[18], sb2[10], sb3[8], sb4[4], sb5[2], sW6f[2], sb6f[1];

    const int tid = threadIdx.x;
    if (tid < 162) sW1[tid] = __ldg((const u64*)W1 + tid);
    if (tid < 90)  sW2[tid] = __ldg((const u64*)W2 + tid);
    if (tid < 40)  sW3[tid] = __ldg((const u64*)W3 + tid);
    if (tid < 16)  sW4[tid] = __ldg((const u64*)W4 + tid);
    if (tid < 4)  { sW5[tid] = __ldg((const u64*)W5 + tid); sb4[tid] = b4[tid]; }
    if (tid < 18)  sb1[tid] = b1[tid];
    if (tid < 10)  sb2[tid] = b2[tid];
    if (tid < 8)   sb3[tid] = b3[tid];
    if (tid < 2)  { sb5[tid] = b5[tid]; sW6f[tid] = W6[tid]; }
    if (tid == 0)  sb6f[0] = b6[0];

    const size_t base = (size_t)blockIdx.x * 256;
    const u64* gh = (const u64*)g_h2 + base * 9;
    #pragma unroll
    for (int i = 0; i < 9; ++i) sROW[tid + i * 256] = __ldg(&gh[tid + i * 256]);
    __syncthreads();

    u64 a0[9];
    #pragma unroll
    for (int m = 0; m < 9; ++m) a0[m] = sROW[tid * 9 + m];

    float a1[18];
    #pragma unroll
    for (int j = 0; j < 18; ++j) {
        u64 acc = pack2(sb1[j], 0.f), accb = 0ull;
        #pragma unroll
        for (int m = 0; m < 9; ++m) fma2((m & 1) ? accb : acc, sW1[j * 9 + m], a0[m]);
        a1[j] = fmaxf(hsum2(add2(acc, accb)), 0.f);
    }
    u64 a1p[9];
    #pragma unroll
    for (int m = 0; m < 9; ++m) a1p[m] = pack2(a1[2 * m], a1[2 * m + 1]);

    float a2[10];
    #pragma unroll
    for (int j = 0; j < 10; ++j) {
        u64 acc = pack2(sb2[j], 0.f), accb = 0ull;
        #pragma unroll
        for (int m = 0; m < 9; ++m) fma2((m & 1) ? accb : acc, sW2[j * 9 + m], a1p[m]);
        a2[j] = fmaxf(hsum2(add2(acc, accb)), 0.f);
    }
    u64 a2p[5];
    #pragma unroll
    for (int m = 0; m < 5; ++m) a2p[m] = pack2(a2[2 * m], a2[2 * m + 1]);

    float a3[8];
    #pragma unroll
    for (int j = 0; j < 8; ++j) {
        u64 acc = pack2(sb3[j], 0.f), accb = 0ull;
        #pragma unroll
        for (int m = 0; m < 5; ++m) fma2((m & 1) ? accb : acc, sW3[j * 5 + m], a2p[m]);
        a3[j] = fmaxf(hsum2(add2(acc, accb)), 0.f);
    }
    u64 a3p[4];
    #pragma unroll
    for (int m = 0; m < 4; ++m) a3p[m] = pack2(a3[2 * m], a3[2 * m + 1]);

    float a4[4];
    #pragma unroll
    for (int j = 0; j < 4; ++j) {
        u64 acc = pack2(sb4[j], 0.f), accb = 0ull;
        #pragma unroll
        for (int m = 0; m < 4; ++m) fma2((m & 1) ? accb : acc, sW4[j * 4 + m], a3p[m]);
        a4[j] = fmaxf(hsum2(add2(acc, accb)), 0.f);
    }
    u64 a4p[2] = { pack2(a4[0], a4[1]), pack2(a4[2], a4[3]) };

    float a5[2];
    #pragma unroll
    for (int j = 0; j < 2; ++j) {
        u64 acc = pack2(sb5[j], 0.f);
        fma2(acc, sW5[j * 2 + 0], a4p[0]);
        fma2(acc, sW5[j * 2 + 1], a4p[1]);
        a5[j] = fmaxf(hsum2(acc), 0.f);
    }
    out[base + tid] = fmaf(a5[0], sW6f[0], fmaf(a5[1], sW6f[1], sb6f[0]));
}

// ---------------------------------------------------------------------------
// Launch
// ---------------------------------------------------------------------------
extern "C" void kernel_launch(void* const* d_in, const int* in_sizes, int n_in,
                              void* d_out, int out_size)
{
    const float* input  = (const float*)d_in[0];
    const float* hidden = (const float*)d_in[1];
    const float* Wih0 = (const float*)d_in[2];
    const float* bih0 = (const float*)d_in[3];
    const float* Whh0 = (const float*)d_in[4];
    const float* bhh0 = (const float*)d_in[5];
    const float* Wih1 = (const float*)d_in[6];
    const float* bih1 = (const float*)d_in[7];
    const float* Whh1 = (const float*)d_in[8];
    const float* bhh1 = (const float*)d_in[9];
    const float* Wih2 = (const float*)d_in[10];
    const float* bih2 = (const float*)d_in[11];
    const float* Whh2 = (const float*)d_in[12];
    const float* bhh2 = (const float*)d_in[13];
    const float* W1 = (const float*)d_in[14];
    const float* b1 = (const float*)d_in[15];
    const float* W2 = (const float*)d_in[16];
    const float* b2 = (const float*)d_in[17];
    const float* W3 = (const float*)d_in[18];
    const float* b3 = (const float*)d_in[19];
    const float* W4 = (const float*)d_in[20];
    const float* b4 = (const float*)d_in[21];
    const float* W5 = (const float*)d_in[22];
    const float* b5 = (const float*)d_in[23];
    const float* W6 = (const float*)d_in[24];
    const float* b6 = (const float*)d_in[25];

    float* out = (float*)d_out;
    const int write_hidden = (out_size >= B_ * S_ + 3 * B_ * H_) ? 1 : 0;

    xw0_kernel<<<(B_ * S_) / 128, 128>>>(input, Wih0, bih0, bhh0);

    rnn_scan_kernel<<<B_ / 2, 256>>>(hidden, Whh0,
                                     Wih1, bih1, Whh1, bhh1,
                                     Wih2, bih2, Whh2, bhh2,
                                     out, write_hidden);

    mlp_head_kernel<<<(B_ * S_) / 256, 256>>>(W1, b1, W2, b2, W3, b3,
                                              W4, b4, W5, b5, W6, b6, out);
}